// round 1
// baseline (speedup 1.0000x reference)
#include <cuda_runtime.h>
#include <math.h>

#define NTOK 65536
#define GOUT 1024
#define NE   8
#define SH   64
#define AH   256
#define GH   64
// Each token picks exactly 2 experts -> 131072 rows; pad each expert segment to 128.
#define CAP  (131072 + NE*128)
#define MT   (CAP/128)   // 1032 M-tiles

// ---------------- scratch (device globals; no runtime allocation) ----------------
__device__ int   d_cnt[NE];
__device__ int   d_off[NE+1];
__device__ int   d_cursor[NE];
__device__ float d_imp[NE];
__device__ int   d_e1[NTOK], d_e2[NTOK];
__device__ float d_g1[NTOK], d_g2[NTOK], d_iso1[NTOK], d_iso2[NTOK];
__device__ int   d_crow[CAP];
__device__ float d_cgate[CAP];
__device__ float d_ciso[CAP];
__device__ float d_A2[(size_t)CAP * AH];   // 135 MB activation scratch

// ---------------- init ----------------
__global__ void k_init() {
    int t = threadIdx.x;
    if (t < NE) { d_cnt[t] = 0; d_imp[t] = 0.f; }
}

// ---------------- gate net + top2 + S-net (iso) per token ----------------
// one block (64 threads) per token
__global__ void k_gate_snet(
    const float* __restrict__ x,
    const float* __restrict__ S_W1, const float* __restrict__ S_b1,
    const float* __restrict__ S_W2, const float* __restrict__ S_b2,
    const float* __restrict__ S_W3, const float* __restrict__ S_b3,
    const float* __restrict__ g_W1, const float* __restrict__ g_b1,
    const float* __restrict__ g_W2, const float* __restrict__ g_b2,
    const float* __restrict__ g_W3, const float* __restrict__ g_b3)
{
    int t   = blockIdx.x;
    int tid = threadIdx.x;

    __shared__ float sh[GH];
    __shared__ float sh2[GH];
    __shared__ float red[SH];
    __shared__ float lg[NE];
    __shared__ int   se[2];
    __shared__ float sg[2];

    float x0 = x[2*t], x1 = x[2*t + 1];

    // gate layer 1
    float h = fmaxf(0.f, x0 * g_W1[2*tid] + x1 * g_W1[2*tid+1] + g_b1[tid]);
    sh[tid] = h;
    __syncthreads();

    // gate layer 2 (float4 weight loads)
    {
        float acc = g_b2[tid];
        const float4* w4 = (const float4*)(g_W2 + tid * GH);
        const float4* s4 = (const float4*)sh;
        #pragma unroll
        for (int i = 0; i < GH/4; i++) {
            float4 w = w4[i], s = s4[i];
            acc += w.x*s.x + w.y*s.y + w.z*s.z + w.w*s.w;
        }
        sh2[tid] = fmaxf(0.f, acc);
    }
    __syncthreads();

    // gate layer 3 -> logits
    if (tid < NE) {
        float acc = g_b3[tid];
        const float4* w4 = (const float4*)(g_W3 + tid * GH);
        const float4* s4 = (const float4*)sh2;
        #pragma unroll
        for (int i = 0; i < GH/4; i++) {
            float4 w = w4[i], s = s4[i];
            acc += w.x*s.x + w.y*s.y + w.z*s.z + w.w*s.w;
        }
        lg[tid] = acc;
    }
    __syncthreads();

    if (tid == 0) {
        int b1i = 0; float v1 = lg[0];
        #pragma unroll
        for (int e = 1; e < NE; e++) if (lg[e] > v1) { v1 = lg[e]; b1i = e; }
        int b2i = -1; float v2 = -1e30f;
        #pragma unroll
        for (int e = 0; e < NE; e++) if (e != b1i && lg[e] > v2) { v2 = lg[e]; b2i = e; }
        float ed  = expf(v2 - v1);
        float den = 1.f + ed;
        sg[0] = 1.f / den;
        sg[1] = ed / den;
        se[0] = b1i; se[1] = b2i;
        atomicAdd(&d_cnt[b1i], 1);
        atomicAdd(&d_cnt[b2i], 1);
    }
    __syncthreads();

    // S-net for the two chosen experts
    for (int q = 0; q < 2; q++) {
        int e = se[q];
        float s1 = fmaxf(0.f, x0 * S_W1[e*SH*2 + 2*tid] + x1 * S_W1[e*SH*2 + 2*tid + 1]
                              + S_b1[e*SH + tid]);
        sh[tid] = s1;
        __syncthreads();

        float a2 = S_b2[e*SH + tid];
        const float4* w4 = (const float4*)(S_W2 + (size_t)e*SH*SH + tid*SH);
        const float4* s4 = (const float4*)sh;
        #pragma unroll
        for (int i = 0; i < SH/4; i++) {
            float4 w = w4[i], s = s4[i];
            a2 += w.x*s.x + w.y*s.y + w.z*s.z + w.w*s.w;
        }
        a2 = fmaxf(0.f, a2);
        red[tid] = a2 * S_W3[e*SH + tid];
        __syncthreads();
        #pragma unroll
        for (int s = 32; s > 0; s >>= 1) {
            if (tid < s) red[tid] += red[tid + s];
            __syncthreads();
        }
        if (tid == 0) {
            float iso = red[0] + S_b3[e];
            if (q == 0) { d_iso1[t] = iso; d_e1[t] = e; d_g1[t] = sg[0]; }
            else        { d_iso2[t] = iso; d_e2[t] = e; d_g2[t] = sg[1]; }
        }
        __syncthreads();
    }
}

// ---------------- deterministic importance reduction (one block per expert) ------
__global__ void k_imp() {
    int e = blockIdx.x;
    int tid = threadIdx.x;
    __shared__ float red[256];
    float s = 0.f;
    for (int t = tid; t < NTOK; t += 256) {
        if (d_e1[t] == e) s += d_g1[t];
        if (d_e2[t] == e) s += d_g2[t];
    }
    red[tid] = s;
    __syncthreads();
    #pragma unroll
    for (int k = 128; k > 0; k >>= 1) {
        if (tid < k) red[tid] += red[tid + k];
        __syncthreads();
    }
    if (tid == 0) d_imp[e] = red[0];
}

// ---------------- offsets + padding + loss (single block) ----------------
__global__ void k_off(float* __restrict__ out, long long loss_idx) {
    __shared__ int soff[NE+1];
    int tid = threadIdx.x;
    if (tid == 0) {
        int o = 0;
        for (int e = 0; e < NE; e++) {
            soff[e] = o; d_off[e] = o; d_cursor[e] = o;
            o += ((d_cnt[e] + 127) / 128) * 128;
        }
        soff[NE] = o; d_off[NE] = o;

        // load-balancing loss (load[e] == cnt[e] since softmax gates > 0)
        float mi = 0.f, ml = 0.f;
        for (int e = 0; e < NE; e++) { mi += d_imp[e]; ml += (float)d_cnt[e]; }
        mi /= (float)NE; ml /= (float)NE;
        float vi = 0.f, vl = 0.f;
        for (int e = 0; e < NE; e++) {
            float di = d_imp[e] - mi;        vi += di * di;
            float dl = (float)d_cnt[e] - ml; vl += dl * dl;
        }
        vi /= (float)(NE - 1); vl /= (float)(NE - 1);
        float loss = (vi / (mi*mi + 1e-10f) + vl / (ml*ml + 1e-10f)) * 0.01f;
        out[loss_idx] = loss;
    }
    __syncthreads();
    // fill padding rows
    for (int e = 0; e < NE; e++) {
        int s  = soff[e] + d_cnt[e];
        int en = soff[e+1];
        for (int i = s + tid; i < en; i += blockDim.x) {
            d_crow[i] = -1; d_cgate[i] = 0.f; d_ciso[i] = 0.f;
        }
    }
}

// ---------------- scatter tokens into per-expert compact row lists ----------------
__global__ void k_scatter() {
    int t = blockIdx.x * blockDim.x + threadIdx.x;
    if (t >= NTOK) return;
    int p = atomicAdd(&d_cursor[d_e1[t]], 1);
    d_crow[p] = t; d_cgate[p] = d_g1[t]; d_ciso[p] = d_iso1[t];
    p = atomicAdd(&d_cursor[d_e2[t]], 1);
    d_crow[p] = t; d_cgate[p] = d_g2[t]; d_ciso[p] = d_iso2[t];
}

// ---------------- GEMM1: A2 = relu(relu(iso*W1+b1) @ W2^T + b2) ----------------
// A operand generated on the fly from the scalar iso per row.
// grid: (2 n-tiles, MT m-tiles), 256 threads, 128x128x16 tiles
__global__ __launch_bounds__(256) void k_gemm1(
    const float* __restrict__ A_W1, const float* __restrict__ A_b1,
    const float* __restrict__ A_W2, const float* __restrict__ A_b2)
{
    int m0 = blockIdx.y * 128;
    if (m0 >= d_off[NE]) return;
    int e = 0;
    while (m0 >= d_off[e+1]) e++;
    int n0 = blockIdx.x * 128;

    __shared__ float s_iso[128];
    __shared__ float s_w1[AH], s_b1v[AH];
    __shared__ float As[16][128];
    __shared__ float Bs[16][128];

    int tid = threadIdx.x;
    int ty = tid >> 4, tx = tid & 15;

    if (tid < 128) s_iso[tid] = d_ciso[m0 + tid];
    s_w1[tid]  = A_W1[e*AH + tid];
    s_b1v[tid] = A_b1[e*AH + tid];

    const float* W2e = A_W2 + (size_t)e * AH * AH;

    float acc[8][8];
    #pragma unroll
    for (int i = 0; i < 8; i++)
        #pragma unroll
        for (int j = 0; j < 8; j++) acc[i][j] = 0.f;

    for (int k0 = 0; k0 < AH; k0 += 16) {
        __syncthreads();
        // build A tile from iso (rank-1 layer 1 + relu)
        #pragma unroll
        for (int r = 0; r < 8; r++) {
            int idx = tid + r * 256;
            int kk = idx >> 7, m = idx & 127;
            As[kk][m] = fmaxf(0.f, s_iso[m] * s_w1[k0 + kk] + s_b1v[k0 + kk]);
        }
        // load B tile (W2 rows, k-contiguous)
        #pragma unroll
        for (int r = 0; r < 2; r++) {
            int q = tid + r * 256;
            int n = q >> 2, kq = q & 3;
            float4 v = *(const float4*)&W2e[(size_t)(n0 + n) * AH + k0 + kq*4];
            Bs[kq*4+0][n] = v.x; Bs[kq*4+1][n] = v.y;
            Bs[kq*4+2][n] = v.z; Bs[kq*4+3][n] = v.w;
        }
        __syncthreads();
        #pragma unroll
        for (int kk = 0; kk < 16; kk++) {
            float a[8], b[8];
            #pragma unroll
            for (int i = 0; i < 8; i++) a[i] = As[kk][ty*8 + i];
            #pragma unroll
            for (int j = 0; j < 8; j++) b[j] = Bs[kk][tx*8 + j];
            #pragma unroll
            for (int i = 0; i < 8; i++)
                #pragma unroll
                for (int j = 0; j < 8; j++) acc[i][j] += a[i] * b[j];
        }
    }

    const float* b2 = A_b2 + e*AH + n0;
    #pragma unroll
    for (int i = 0; i < 8; i++) {
        int row = m0 + ty*8 + i;
        float* dst = &d_A2[(size_t)row * AH + n0 + tx*8];
        #pragma unroll
        for (int j = 0; j < 8; j++)
            dst[j] = fmaxf(0.f, acc[i][j] + b2[tx*8 + j]);
    }
}

// ---------------- GEMM2: out[tok] += gate * (A2 @ W3^T + b3) ----------------
// grid: (8 n-tiles, MT m-tiles), 256 threads, 128x128x16 tiles
__global__ __launch_bounds__(256) void k_gemm2(
    const float* __restrict__ A_W3, const float* __restrict__ A_b3,
    float* __restrict__ out)
{
    int m0 = blockIdx.y * 128;
    if (m0 >= d_off[NE]) return;
    int e = 0;
    while (m0 >= d_off[e+1]) e++;
    int n0 = blockIdx.x * 128;

    __shared__ int   s_tok[128];
    __shared__ float s_g[128];
    __shared__ float As[16][128];
    __shared__ float Bs[16][128];

    int tid = threadIdx.x;
    int ty = tid >> 4, tx = tid & 15;

    if (tid < 128) { s_tok[tid] = d_crow[m0 + tid]; s_g[tid] = d_cgate[m0 + tid]; }

    const float* W3e   = A_W3 + (size_t)e * GOUT * AH;
    const float* A2b   = d_A2 + (size_t)m0 * AH;

    float acc[8][8];
    #pragma unroll
    for (int i = 0; i < 8; i++)
        #pragma unroll
        for (int j = 0; j < 8; j++) acc[i][j] = 0.f;

    for (int k0 = 0; k0 < AH; k0 += 16) {
        __syncthreads();
        #pragma unroll
        for (int r = 0; r < 2; r++) {
            int q = tid + r * 256;
            int m = q >> 2, kq = q & 3;
            float4 v = *(const float4*)&A2b[(size_t)m * AH + k0 + kq*4];
            As[kq*4+0][m] = v.x; As[kq*4+1][m] = v.y;
            As[kq*4+2][m] = v.z; As[kq*4+3][m] = v.w;
        }
        #pragma unroll
        for (int r = 0; r < 2; r++) {
            int q = tid + r * 256;
            int n = q >> 2, kq = q & 3;
            float4 v = *(const float4*)&W3e[(size_t)(n0 + n) * AH + k0 + kq*4];
            Bs[kq*4+0][n] = v.x; Bs[kq*4+1][n] = v.y;
            Bs[kq*4+2][n] = v.z; Bs[kq*4+3][n] = v.w;
        }
        __syncthreads();
        #pragma unroll
        for (int kk = 0; kk < 16; kk++) {
            float a[8], b[8];
            #pragma unroll
            for (int i = 0; i < 8; i++) a[i] = As[kk][ty*8 + i];
            #pragma unroll
            for (int j = 0; j < 8; j++) b[j] = Bs[kk][tx*8 + j];
            #pragma unroll
            for (int i = 0; i < 8; i++)
                #pragma unroll
                for (int j = 0; j < 8; j++) acc[i][j] += a[i] * b[j];
        }
    }

    const float* b3 = A_b3 + e*GOUT + n0;
    #pragma unroll
    for (int i = 0; i < 8; i++) {
        int tok = s_tok[ty*8 + i];
        if (tok < 0) continue;
        float g = s_g[ty*8 + i];
        float* orow = out + (size_t)tok * GOUT + n0 + tx*8;
        #pragma unroll
        for (int j = 0; j < 8; j++)
            atomicAdd(&orow[j], g * (acc[i][j] + b3[tx*8 + j]));
    }
}

// ---------------- launch ----------------
extern "C" void kernel_launch(void* const* d_in, const int* in_sizes, int n_in,
                              void* d_out, int out_size)
{
    const float* x    = (const float*)d_in[0];
    const float* S_W1 = (const float*)d_in[1];
    const float* S_b1 = (const float*)d_in[2];
    const float* S_W2 = (const float*)d_in[3];
    const float* S_b2 = (const float*)d_in[4];
    const float* S_W3 = (const float*)d_in[5];
    const float* S_b3 = (const float*)d_in[6];
    const float* A_W1 = (const float*)d_in[7];
    const float* A_b1 = (const float*)d_in[8];
    const float* A_W2 = (const float*)d_in[9];
    const float* A_b2 = (const float*)d_in[10];
    const float* A_W3 = (const float*)d_in[11];
    const float* A_b3 = (const float*)d_in[12];
    const float* g_W1 = (const float*)d_in[13];
    const float* g_b1 = (const float*)d_in[14];
    const float* g_W2 = (const float*)d_in[15];
    const float* g_b2 = (const float*)d_in[16];
    const float* g_W3 = (const float*)d_in[17];
    const float* g_b3 = (const float*)d_in[18];
    float* out = (float*)d_out;

    cudaMemsetAsync(d_out, 0, (size_t)out_size * sizeof(float), 0);
    k_init<<<1, 32>>>();
    k_gate_snet<<<NTOK, 64>>>(x, S_W1, S_b1, S_W2, S_b2, S_W3, S_b3,
                              g_W1, g_b1, g_W2, g_b2, g_W3, g_b3);
    k_imp<<<NE, 256>>>();
    k_off<<<1, 128>>>(out, (long long)out_size - 1);
    k_scatter<<<(NTOK + 255) / 256, 256>>>();
    k_gemm1<<<dim3(2, MT), 256>>>(A_W1, A_b1, A_W2, A_b2);
    k_gemm2<<<dim3(8, MT), 256>>>(A_W3, A_b3, out);
}

// round 2
// speedup vs baseline: 1.5309x; 1.5309x over previous
#include <cuda_runtime.h>
#include <math.h>
#include <stdint.h>

#define NTOK 65536
#define GOUT 1024
#define NE   8
#define SH   64
#define AH   256
#define GH   64
#define NSEG 16
// 16 segments (q * 8 + e), each padded to 128 rows
#define CAP  (131072 + NSEG*128)
#define MT1  (CAP/128)                    // 1040
#define MT2  ((NTOK + NE*128)/128)        // 520 per q-group

// ---------------- scratch (device globals; no runtime allocation) ----------------
__device__ int   d_cnt[NSEG];
__device__ int   d_off[NSEG+1];
__device__ int   d_cursor[NSEG];
__device__ float d_imp[NE];
__device__ int   d_e1[NTOK], d_e2[NTOK];
__device__ float d_g1[NTOK], d_g2[NTOK], d_iso1[NTOK], d_iso2[NTOK];
__device__ int   d_crow[CAP];
__device__ float d_cgate[CAP];
__device__ float d_ciso[CAP];
__device__ float d_A2[(size_t)CAP * AH];   // activation scratch

// ---------------- helpers ----------------
__device__ __forceinline__ uint32_t f2tf32(float f) {
    uint32_t u;
    asm volatile("cvt.rna.tf32.f32 %0, %1;" : "=r"(u) : "f"(f));
    return u;
}

__device__ __forceinline__ void mma_tf32(float* c, const uint32_t* a, const uint32_t* b) {
    asm volatile(
        "mma.sync.aligned.m16n8k8.row.col.f32.tf32.tf32.f32 "
        "{%0,%1,%2,%3}, {%4,%5,%6,%7}, {%8,%9}, {%0,%1,%2,%3};\n"
        : "+f"(c[0]), "+f"(c[1]), "+f"(c[2]), "+f"(c[3])
        : "r"(a[0]), "r"(a[1]), "r"(a[2]), "r"(a[3]),
          "r"(b[0]), "r"(b[1]));
}

// ---------------- init ----------------
__global__ void k_init() {
    int t = threadIdx.x;
    if (t < NSEG) d_cnt[t] = 0;
    if (t < NE)   d_imp[t] = 0.f;
}

// ---------------- gate net + top2 + S-net (iso) per token ----------------
__global__ void k_gate_snet(
    const float* __restrict__ x,
    const float* __restrict__ S_W1, const float* __restrict__ S_b1,
    const float* __restrict__ S_W2, const float* __restrict__ S_b2,
    const float* __restrict__ S_W3, const float* __restrict__ S_b3,
    const float* __restrict__ g_W1, const float* __restrict__ g_b1,
    const float* __restrict__ g_W2, const float* __restrict__ g_b2,
    const float* __restrict__ g_W3, const float* __restrict__ g_b3)
{
    int t   = blockIdx.x;
    int tid = threadIdx.x;

    __shared__ float sh[GH];
    __shared__ float sh2[GH];
    __shared__ float red[SH];
    __shared__ float lg[NE];
    __shared__ int   se[2];
    __shared__ float sg[2];

    float x0 = x[2*t], x1 = x[2*t + 1];

    float h = fmaxf(0.f, x0 * g_W1[2*tid] + x1 * g_W1[2*tid+1] + g_b1[tid]);
    sh[tid] = h;
    __syncthreads();

    {
        float acc = g_b2[tid];
        const float4* w4 = (const float4*)(g_W2 + tid * GH);
        const float4* s4 = (const float4*)sh;
        #pragma unroll
        for (int i = 0; i < GH/4; i++) {
            float4 w = w4[i], s = s4[i];
            acc += w.x*s.x + w.y*s.y + w.z*s.z + w.w*s.w;
        }
        sh2[tid] = fmaxf(0.f, acc);
    }
    __syncthreads();

    if (tid < NE) {
        float acc = g_b3[tid];
        const float4* w4 = (const float4*)(g_W3 + tid * GH);
        const float4* s4 = (const float4*)sh2;
        #pragma unroll
        for (int i = 0; i < GH/4; i++) {
            float4 w = w4[i], s = s4[i];
            acc += w.x*s.x + w.y*s.y + w.z*s.z + w.w*s.w;
        }
        lg[tid] = acc;
    }
    __syncthreads();

    if (tid == 0) {
        int b1i = 0; float v1 = lg[0];
        #pragma unroll
        for (int e = 1; e < NE; e++) if (lg[e] > v1) { v1 = lg[e]; b1i = e; }
        int b2i = -1; float v2 = -1e30f;
        #pragma unroll
        for (int e = 0; e < NE; e++) if (e != b1i && lg[e] > v2) { v2 = lg[e]; b2i = e; }
        float ed  = expf(v2 - v1);
        float den = 1.f + ed;
        sg[0] = 1.f / den;
        sg[1] = ed / den;
        se[0] = b1i; se[1] = b2i;
        atomicAdd(&d_cnt[b1i], 1);       // q=0 segment
        atomicAdd(&d_cnt[8 + b2i], 1);   // q=1 segment
    }
    __syncthreads();

    for (int q = 0; q < 2; q++) {
        int e = se[q];
        float s1 = fmaxf(0.f, x0 * S_W1[e*SH*2 + 2*tid] + x1 * S_W1[e*SH*2 + 2*tid + 1]
                              + S_b1[e*SH + tid]);
        sh[tid] = s1;
        __syncthreads();

        float a2 = S_b2[e*SH + tid];
        const float4* w4 = (const float4*)(S_W2 + (size_t)e*SH*SH + tid*SH);
        const float4* s4 = (const float4*)sh;
        #pragma unroll
        for (int i = 0; i < SH/4; i++) {
            float4 w = w4[i], s = s4[i];
            a2 += w.x*s.x + w.y*s.y + w.z*s.z + w.w*s.w;
        }
        a2 = fmaxf(0.f, a2);
        red[tid] = a2 * S_W3[e*SH + tid];
        __syncthreads();
        #pragma unroll
        for (int s = 32; s > 0; s >>= 1) {
            if (tid < s) red[tid] += red[tid + s];
            __syncthreads();
        }
        if (tid == 0) {
            float iso = red[0] + S_b3[e];
            if (q == 0) { d_iso1[t] = iso; d_e1[t] = e; d_g1[t] = sg[0]; }
            else        { d_iso2[t] = iso; d_e2[t] = e; d_g2[t] = sg[1]; }
        }
        __syncthreads();
    }
}

// ---------------- deterministic importance reduction ----------------
__global__ void k_imp() {
    int e = blockIdx.x;
    int tid = threadIdx.x;
    __shared__ float red[256];
    float s = 0.f;
    for (int t = tid; t < NTOK; t += 256) {
        if (d_e1[t] == e) s += d_g1[t];
        if (d_e2[t] == e) s += d_g2[t];
    }
    red[tid] = s;
    __syncthreads();
    #pragma unroll
    for (int k = 128; k > 0; k >>= 1) {
        if (tid < k) red[tid] += red[tid + k];
        __syncthreads();
    }
    if (tid == 0) d_imp[e] = red[0];
}

// ---------------- offsets + padding + loss ----------------
__global__ void k_off(float* __restrict__ out, long long loss_idx) {
    __shared__ int soff[NSEG+1];
    int tid = threadIdx.x;
    if (tid == 0) {
        int o = 0;
        for (int s = 0; s < NSEG; s++) {
            soff[s] = o; d_off[s] = o; d_cursor[s] = o;
            o += ((d_cnt[s] + 127) / 128) * 128;
        }
        soff[NSEG] = o; d_off[NSEG] = o;

        float mi = 0.f, ml = 0.f;
        float ld[NE];
        for (int e = 0; e < NE; e++) {
            ld[e] = (float)(d_cnt[e] + d_cnt[8 + e]);
            mi += d_imp[e]; ml += ld[e];
        }
        mi /= (float)NE; ml /= (float)NE;
        float vi = 0.f, vl = 0.f;
        for (int e = 0; e < NE; e++) {
            float di = d_imp[e] - mi; vi += di * di;
            float dl = ld[e] - ml;    vl += dl * dl;
        }
        vi /= (float)(NE - 1); vl /= (float)(NE - 1);
        float loss = (vi / (mi*mi + 1e-10f) + vl / (ml*ml + 1e-10f)) * 0.01f;
        out[loss_idx] = loss;
    }
    __syncthreads();
    for (int s = 0; s < NSEG; s++) {
        int b  = soff[s] + d_cnt[s];
        int en = soff[s+1];
        for (int i = b + tid; i < en; i += blockDim.x) {
            d_crow[i] = -1; d_cgate[i] = 0.f; d_ciso[i] = 0.f;
        }
    }
}

// ---------------- scatter into per-(q,expert) compact rows ----------------
__global__ void k_scatter() {
    int t = blockIdx.x * blockDim.x + threadIdx.x;
    if (t >= NTOK) return;
    int p = atomicAdd(&d_cursor[d_e1[t]], 1);
    d_crow[p] = t; d_cgate[p] = d_g1[t]; d_ciso[p] = d_iso1[t];
    p = atomicAdd(&d_cursor[8 + d_e2[t]], 1);
    d_crow[p] = t; d_cgate[p] = d_g2[t]; d_ciso[p] = d_iso2[t];
}

// ======================= TF32 MMA GEMMs =======================
// 128x128 tile, 256 threads = 8 warps as 4(m) x 2(n); warp tile 32m x 64n.
// smem tiles [k=16][m/n=128] with +8 pad (row stride 136) -> conflict-free frag LDS.

#define STS_A(buf) {                                                      \
    As[buf][skb+0][sm]=f2tf32(ra0.x); As[buf][skb+1][sm]=f2tf32(ra0.y);   \
    As[buf][skb+2][sm]=f2tf32(ra0.z); As[buf][skb+3][sm]=f2tf32(ra0.w);   \
    As[buf][skb+4][sm]=f2tf32(ra1.x); As[buf][skb+5][sm]=f2tf32(ra1.y);   \
    As[buf][skb+6][sm]=f2tf32(ra1.z); As[buf][skb+7][sm]=f2tf32(ra1.w); }

#define STS_B(buf) {                                                      \
    Bs[buf][skb+0][sm]=f2tf32(rb0.x); Bs[buf][skb+1][sm]=f2tf32(rb0.y);   \
    Bs[buf][skb+2][sm]=f2tf32(rb0.z); Bs[buf][skb+3][sm]=f2tf32(rb0.w);   \
    Bs[buf][skb+4][sm]=f2tf32(rb1.x); Bs[buf][skb+5][sm]=f2tf32(rb1.y);   \
    Bs[buf][skb+6][sm]=f2tf32(rb1.z); Bs[buf][skb+7][sm]=f2tf32(rb1.w); }

#define COMPUTE_CHUNK(cur) {                                              \
    _Pragma("unroll")                                                     \
    for (int kk = 0; kk < 16; kk += 8) {                                  \
        uint32_t af[2][4], bf[8][2];                                      \
        _Pragma("unroll")                                                 \
        for (int mf = 0; mf < 2; mf++) {                                  \
            int mb = wm + mf*16 + g;                                      \
            af[mf][0] = As[cur][kk+tq  ][mb];                             \
            af[mf][1] = As[cur][kk+tq  ][mb+8];                           \
            af[mf][2] = As[cur][kk+tq+4][mb];                             \
            af[mf][3] = As[cur][kk+tq+4][mb+8];                           \
        }                                                                 \
        _Pragma("unroll")                                                 \
        for (int nf = 0; nf < 8; nf++) {                                  \
            int nb = wn + nf*8 + g;                                       \
            bf[nf][0] = Bs[cur][kk+tq  ][nb];                             \
            bf[nf][1] = Bs[cur][kk+tq+4][nb];                             \
        }                                                                 \
        _Pragma("unroll")                                                 \
        for (int mf = 0; mf < 2; mf++)                                    \
            _Pragma("unroll")                                             \
            for (int nf = 0; nf < 8; nf++)                                \
                mma_tf32(acc[mf][nf], af[mf], bf[nf]);                    \
    } }

// ---------------- GEMM1: A2 = relu(relu(iso*W1+b1) @ W2^T + b2) ----------------
__global__ __launch_bounds__(256) void k_gemm1(
    const float* __restrict__ A_W1, const float* __restrict__ A_b1,
    const float* __restrict__ A_W2, const float* __restrict__ A_b2)
{
    int m0 = blockIdx.y * 128;
    if (m0 >= d_off[NSEG]) return;
    int s = 0;
    while (m0 >= d_off[s+1]) s++;
    int e = s & 7;
    int n0 = blockIdx.x * 128;

    __shared__ uint32_t As[2][16][136];
    __shared__ uint32_t Bs[2][16][136];
    __shared__ float s_iso[128];
    __shared__ float s_w1[AH], s_b1v[AH];

    int tid = threadIdx.x;
    int sm = tid & 127, skb = (tid >> 7) * 8;
    int wid = tid >> 5, lane = tid & 31;
    int wm = (wid >> 1) * 32, wn = (wid & 1) * 64;
    int g = lane >> 2, tq = lane & 3;

    if (tid < 128) s_iso[tid] = d_ciso[m0 + tid];
    s_w1[tid]  = A_W1[e*AH + tid];
    s_b1v[tid] = A_b1[e*AH + tid];
    __syncthreads();

    const float* Bbase = A_W2 + ((size_t)e*AH + n0 + sm) * AH + skb;
    float iso = s_iso[sm];

    float4 rb0, rb1;
    rb0 = *(const float4*)(Bbase);
    rb1 = *(const float4*)(Bbase + 4);
    // generate A chunk0
    #pragma unroll
    for (int i = 0; i < 8; i++) {
        float v = fmaxf(0.f, iso * s_w1[skb+i] + s_b1v[skb+i]);
        As[0][skb+i][sm] = f2tf32(v);
    }
    STS_B(0);
    __syncthreads();

    float acc[2][8][4];
    #pragma unroll
    for (int mf = 0; mf < 2; mf++)
        #pragma unroll
        for (int nf = 0; nf < 8; nf++)
            #pragma unroll
            for (int i = 0; i < 4; i++) acc[mf][nf][i] = 0.f;

    for (int c = 0; c < 16; c++) {
        int cur = c & 1;
        if (c + 1 < 16) {
            rb0 = *(const float4*)(Bbase + (c+1)*16);
            rb1 = *(const float4*)(Bbase + (c+1)*16 + 4);
        }
        COMPUTE_CHUNK(cur);
        if (c + 1 < 16) {
            int nxt = cur ^ 1;
            int kb2 = (c+1)*16 + skb;
            #pragma unroll
            for (int i = 0; i < 8; i++) {
                float v = fmaxf(0.f, iso * s_w1[kb2+i] + s_b1v[kb2+i]);
                As[nxt][skb+i][sm] = f2tf32(v);
            }
            STS_B(nxt);
        }
        __syncthreads();
    }

    const float* b2p = A_b2 + e*AH + n0 + wn;
    #pragma unroll
    for (int mf = 0; mf < 2; mf++) {
        #pragma unroll
        for (int h = 0; h < 2; h++) {
            int row = m0 + wm + mf*16 + g + h*8;
            float* dst = d_A2 + (size_t)row * AH + n0 + wn;
            #pragma unroll
            for (int nf = 0; nf < 8; nf++) {
                int col = nf*8 + 2*tq;
                float2 v;
                v.x = fmaxf(0.f, acc[mf][nf][2*h+0] + b2p[col]);
                v.y = fmaxf(0.f, acc[mf][nf][2*h+1] + b2p[col+1]);
                *(float2*)&dst[col] = v;
            }
        }
    }
}

// ---------------- GEMM2: out rows; PASS 0: store, PASS 1: load-add-store -------
template<int PASS>
__global__ __launch_bounds__(256) void k_gemm2(
    const float* __restrict__ A_W3, const float* __restrict__ A_b3,
    float* __restrict__ out)
{
    int base = (PASS == 0) ? 0 : d_off[8];
    int lim  = (PASS == 0) ? d_off[8] : d_off[NSEG];
    int m0 = base + blockIdx.y * 128;
    if (m0 >= lim) return;
    int s = 0;
    while (m0 >= d_off[s+1]) s++;
    int e = s & 7;
    int n0 = blockIdx.x * 128;

    __shared__ uint32_t As[2][16][136];
    __shared__ uint32_t Bs[2][16][136];
    __shared__ int   s_tok[128];
    __shared__ float s_gt[128];

    int tid = threadIdx.x;
    int sm = tid & 127, skb = (tid >> 7) * 8;
    int wid = tid >> 5, lane = tid & 31;
    int wm = (wid >> 1) * 32, wn = (wid & 1) * 64;
    int g = lane >> 2, tq = lane & 3;

    if (tid < 128) { s_tok[tid] = d_crow[m0 + tid]; s_gt[tid] = d_cgate[m0 + tid]; }

    const float* Abase = d_A2 + (size_t)(m0 + sm) * AH + skb;
    const float* Bbase = A_W3 + ((size_t)e*GOUT + n0 + sm) * AH + skb;

    float4 ra0, ra1, rb0, rb1;
    ra0 = *(const float4*)(Abase); ra1 = *(const float4*)(Abase + 4);
    rb0 = *(const float4*)(Bbase); rb1 = *(const float4*)(Bbase + 4);
    STS_A(0); STS_B(0);
    __syncthreads();

    float acc[2][8][4];
    #pragma unroll
    for (int mf = 0; mf < 2; mf++)
        #pragma unroll
        for (int nf = 0; nf < 8; nf++)
            #pragma unroll
            for (int i = 0; i < 4; i++) acc[mf][nf][i] = 0.f;

    for (int c = 0; c < 16; c++) {
        int cur = c & 1;
        if (c + 1 < 16) {
            ra0 = *(const float4*)(Abase + (c+1)*16);
            ra1 = *(const float4*)(Abase + (c+1)*16 + 4);
            rb0 = *(const float4*)(Bbase + (c+1)*16);
            rb1 = *(const float4*)(Bbase + (c+1)*16 + 4);
        }
        COMPUTE_CHUNK(cur);
        if (c + 1 < 16) {
            int nxt = cur ^ 1;
            STS_A(nxt); STS_B(nxt);
        }
        __syncthreads();
    }

    const float* b3p = A_b3 + e*GOUT + n0 + wn;
    #pragma unroll
    for (int mf = 0; mf < 2; mf++) {
        #pragma unroll
        for (int h = 0; h < 2; h++) {
            int mr = wm + mf*16 + g + h*8;
            int tok = s_tok[mr];
            if (tok < 0) continue;
            float gt = s_gt[mr];
            float* orow = out + (size_t)tok * GOUT + n0 + wn;
            #pragma unroll
            for (int nf = 0; nf < 8; nf++) {
                int col = nf*8 + 2*tq;
                float vx = gt * (acc[mf][nf][2*h+0] + b3p[col]);
                float vy = gt * (acc[mf][nf][2*h+1] + b3p[col+1]);
                if (PASS == 0) {
                    float2 v; v.x = vx; v.y = vy;
                    *(float2*)&orow[col] = v;
                } else {
                    float2 o = *(const float2*)&orow[col];
                    o.x += vx; o.y += vy;
                    *(float2*)&orow[col] = o;
                }
            }
        }
    }
}

// ---------------- launch ----------------
extern "C" void kernel_launch(void* const* d_in, const int* in_sizes, int n_in,
                              void* d_out, int out_size)
{
    const float* x    = (const float*)d_in[0];
    const float* S_W1 = (const float*)d_in[1];
    const float* S_b1 = (const float*)d_in[2];
    const float* S_W2 = (const float*)d_in[3];
    const float* S_b2 = (const float*)d_in[4];
    const float* S_W3 = (const float*)d_in[5];
    const float* S_b3 = (const float*)d_in[6];
    const float* A_W1 = (const float*)d_in[7];
    const float* A_b1 = (const float*)d_in[8];
    const float* A_W2 = (const float*)d_in[9];
    const float* A_b2 = (const float*)d_in[10];
    const float* A_W3 = (const float*)d_in[11];
    const float* A_b3 = (const float*)d_in[12];
    const float* g_W1 = (const float*)d_in[13];
    const float* g_b1 = (const float*)d_in[14];
    const float* g_W2 = (const float*)d_in[15];
    const float* g_b2 = (const float*)d_in[16];
    const float* g_W3 = (const float*)d_in[17];
    const float* g_b3 = (const float*)d_in[18];
    float* out = (float*)d_out;

    k_init<<<1, 32>>>();
    k_gate_snet<<<NTOK, 64>>>(x, S_W1, S_b1, S_W2, S_b2, S_W3, S_b3,
                              g_W1, g_b1, g_W2, g_b2, g_W3, g_b3);
    k_imp<<<NE, 256>>>();
    k_off<<<1, 128>>>(out, (long long)out_size - 1);
    k_scatter<<<(NTOK + 255) / 256, 256>>>();
    k_gemm1<<<dim3(2, MT1), 256>>>(A_W1, A_b1, A_W2, A_b2);
    k_gemm2<0><<<dim3(8, MT2), 256>>>(A_W3, A_b3, out);
    k_gemm2<1><<<dim3(8, MT2), 256>>>(A_W3, A_b3, out);
}

// round 3
// speedup vs baseline: 2.1870x; 1.4286x over previous
#include <cuda_runtime.h>
#include <math.h>
#include <stdint.h>

#define NTOK 65536
#define GOUT 1024
#define NE   8
#define SH   64
#define AH   256
#define GH   64
#define NSEG 16
#define CAP  (131072 + NSEG*128)          // 133120
#define MT1  (CAP/128)                    // 1040
#define MT2  ((NTOK + NE*128)/128)        // 520 per q-group

// ---------------- scratch ----------------
__device__ int   d_cnt[NSEG];
__device__ int   d_off[NSEG+1];
__device__ int   d_cursor[NSEG];
__device__ float d_imp[NE];
__device__ int   d_e1[NTOK], d_e2[NTOK];
__device__ float d_g1[NTOK], d_g2[NTOK];
__device__ int    d_crow[CAP];
__device__ float  d_cgate[CAP];
__device__ float2 d_cx[CAP];
__device__ float  d_ciso[CAP];
__device__ float d_A2[(size_t)CAP * AH];

// ---------------- helpers ----------------
__device__ __forceinline__ uint32_t f2tf32(float f) {
    uint32_t u;
    asm volatile("cvt.rna.tf32.f32 %0, %1;" : "=r"(u) : "f"(f));
    return u;
}
__device__ __forceinline__ void mma_tf32(float* c, const uint32_t* a, const uint32_t* b) {
    asm volatile(
        "mma.sync.aligned.m16n8k8.row.col.f32.tf32.tf32.f32 "
        "{%0,%1,%2,%3}, {%4,%5,%6,%7}, {%8,%9}, {%0,%1,%2,%3};\n"
        : "+f"(c[0]), "+f"(c[1]), "+f"(c[2]), "+f"(c[3])
        : "r"(a[0]), "r"(a[1]), "r"(a[2]), "r"(a[3]),
          "r"(b[0]), "r"(b[1]));
}

// ---------------- init ----------------
__global__ void k_init() {
    int t = threadIdx.x;
    if (t < NSEG) { d_cnt[t] = 0; d_cursor[t] = 0; }
    if (t < NE)   d_imp[t] = 0.f;
}

// ---------------- gate: lane-owns-a-token, uniform weight broadcasts ----------------
__global__ __launch_bounds__(256) void k_gate(
    const float* __restrict__ x,
    const float* __restrict__ g_W1, const float* __restrict__ g_b1,
    const float* __restrict__ g_W2, const float* __restrict__ g_b2,
    const float* __restrict__ g_W3, const float* __restrict__ g_b3)
{
    __shared__ float W1s[GH*2], b1s[GH], W2s[GH*GH], b2s[GH], W3Ts[GH*8], b3s[NE];
    int tid = threadIdx.x;

    for (int i = tid; i < GH*2;  i += 256) W1s[i] = g_W1[i];
    for (int i = tid; i < GH;    i += 256) { b1s[i] = g_b1[i]; b2s[i] = g_b2[i]; }
    for (int i = tid; i < GH*GH; i += 256) W2s[i] = g_W2[i];
    for (int i = tid; i < NE*GH; i += 256) W3Ts[(i & 63)*8 + (i >> 6)] = g_W3[i];
    if (tid < NE) b3s[tid] = g_b3[tid];
    __syncthreads();

    int t = blockIdx.x * 256 + tid;
    float2 xv = *(const float2*)&x[2*t];
    float x0 = xv.x, x1 = xv.y;

    float h[GH];
    #pragma unroll
    for (int i = 0; i < GH; i++)
        h[i] = fmaxf(0.f, x0 * W1s[2*i] + x1 * W1s[2*i+1] + b1s[i]);

    float lg[NE];
    #pragma unroll
    for (int e = 0; e < NE; e++) lg[e] = b3s[e];

    for (int j = 0; j < GH; j++) {
        float a0 = b2s[j], a1 = 0.f, a2 = 0.f, a3 = 0.f;
        #pragma unroll
        for (int i = 0; i < GH; i += 4) {
            float4 w = *(const float4*)&W2s[j*GH + i];
            a0 += h[i]   * w.x; a1 += h[i+1] * w.y;
            a2 += h[i+2] * w.z; a3 += h[i+3] * w.w;
        }
        float aj = fmaxf(0.f, (a0 + a1) + (a2 + a3));
        float4 wa = *(const float4*)&W3Ts[j*8];
        float4 wb = *(const float4*)&W3Ts[j*8 + 4];
        lg[0] += aj*wa.x; lg[1] += aj*wa.y; lg[2] += aj*wa.z; lg[3] += aj*wa.w;
        lg[4] += aj*wb.x; lg[5] += aj*wb.y; lg[6] += aj*wb.z; lg[7] += aj*wb.w;
    }

    int b1i = 0; float v1 = lg[0];
    #pragma unroll
    for (int e = 1; e < NE; e++) if (lg[e] > v1) { v1 = lg[e]; b1i = e; }
    int b2i = -1; float v2 = -1e30f;
    #pragma unroll
    for (int e = 0; e < NE; e++) if (e != b1i && lg[e] > v2) { v2 = lg[e]; b2i = e; }
    float ed  = __expf(v2 - v1);
    float den = 1.f + ed;
    float g1 = 1.f / den, g2 = ed / den;

    d_e1[t] = b1i; d_e2[t] = b2i; d_g1[t] = g1; d_g2[t] = g2;

    // ballot-aggregated count atomics
    int lane = tid & 31;
    #pragma unroll
    for (int e = 0; e < NE; e++) {
        unsigned m = __ballot_sync(0xffffffffu, b1i == e);
        if (m && lane == (__ffs(m) - 1)) atomicAdd(&d_cnt[e], __popc(m));
        unsigned m2 = __ballot_sync(0xffffffffu, b2i == e);
        if (m2 && lane == (__ffs(m2) - 1)) atomicAdd(&d_cnt[8 + e], __popc(m2));
    }
    atomicAdd(&d_imp[b1i], g1);
    atomicAdd(&d_imp[b2i], g2);
}

// ---------------- prep: offsets + scatter (x gathered) + padding + loss ----------------
__global__ __launch_bounds__(256) void k_prep(
    const float* __restrict__ x, float* __restrict__ out, long long loss_idx)
{
    __shared__ int soff[NSEG+1], scnt[NSEG];
    int tid = threadIdx.x;
    if (tid == 0) {
        int o = 0;
        for (int s = 0; s < NSEG; s++) {
            scnt[s] = d_cnt[s];
            soff[s] = o;
            o += ((scnt[s] + 127) / 128) * 128;
        }
        soff[NSEG] = o;
    }
    __syncthreads();

    int t = blockIdx.x * 256 + tid;
    int e1 = d_e1[t], e2 = d_e2[t];
    float2 xv = *(const float2*)&x[2*t];

    int p = soff[e1] + atomicAdd(&d_cursor[e1], 1);
    d_crow[p] = t; d_cgate[p] = d_g1[t]; d_cx[p] = xv;
    int s2 = 8 + e2;
    p = soff[s2] + atomicAdd(&d_cursor[s2], 1);
    d_crow[p] = t; d_cgate[p] = d_g2[t]; d_cx[p] = xv;

    if (blockIdx.x == 0) {
        if (tid <= NSEG) d_off[tid] = soff[tid];
        // padding rows
        for (int s = 0; s < NSEG; s++) {
            int b  = soff[s] + scnt[s];
            int en = soff[s+1];
            for (int i = b + tid; i < en; i += 256) {
                d_crow[i] = -1; d_cgate[i] = 0.f;
                d_cx[i] = make_float2(0.f, 0.f);
            }
        }
        if (tid == 0) {
            float mi = 0.f, ml = 0.f, ld[NE];
            for (int e = 0; e < NE; e++) {
                ld[e] = (float)(scnt[e] + scnt[8 + e]);
                mi += d_imp[e]; ml += ld[e];
            }
            mi /= (float)NE; ml /= (float)NE;
            float vi = 0.f, vl = 0.f;
            for (int e = 0; e < NE; e++) {
                float di = d_imp[e] - mi; vi += di * di;
                float dl = ld[e] - ml;    vl += dl * dl;
            }
            vi /= (float)(NE - 1); vl /= (float)(NE - 1);
            out[loss_idx] = (vi / (mi*mi + 1e-10f) + vl / (ml*ml + 1e-10f)) * 0.01f;
        }
    }
}

// ---------------- S-net on compact rows: lane-owns-a-row ----------------
__global__ __launch_bounds__(128) void k_snet(
    const float* __restrict__ S_W1, const float* __restrict__ S_b1,
    const float* __restrict__ S_W2, const float* __restrict__ S_b2,
    const float* __restrict__ S_W3, const float* __restrict__ S_b3)
{
    int m0 = blockIdx.x * 128;
    if (m0 >= d_off[NSEG]) return;
    int s = 0;
    while (m0 >= d_off[s+1]) s++;
    int e = s & 7;

    __shared__ float W1s[SH*2], b1s[SH], W2s[SH*SH], b2s[SH], W3s[SH];
    __shared__ float b3sh;
    int tid = threadIdx.x;
    for (int i = tid; i < SH*2;  i += 128) W1s[i] = S_W1[e*SH*2 + i];
    for (int i = tid; i < SH;    i += 128) {
        b1s[i] = S_b1[e*SH + i]; b2s[i] = S_b2[e*SH + i]; W3s[i] = S_W3[e*SH + i];
    }
    for (int i = tid; i < SH*SH; i += 128) W2s[i] = S_W2[(size_t)e*SH*SH + i];
    if (tid == 0) b3sh = S_b3[e];
    __syncthreads();

    float2 xv = d_cx[m0 + tid];
    float x0 = xv.x, x1 = xv.y;

    float h[SH];
    #pragma unroll
    for (int i = 0; i < SH; i++)
        h[i] = fmaxf(0.f, x0 * W1s[2*i] + x1 * W1s[2*i+1] + b1s[i]);

    float iso0 = b3sh, iso1 = 0.f;
    for (int j = 0; j < SH; j += 2) {
        float a0 = b2s[j], a1 = 0.f, c0 = b2s[j+1], c1 = 0.f;
        #pragma unroll
        for (int i = 0; i < SH; i += 4) {
            float4 w = *(const float4*)&W2s[j*SH + i];
            a0 += h[i]   * w.x; a1 += h[i+1] * w.y;
            a0 += h[i+2] * w.z; a1 += h[i+3] * w.w;
            float4 u = *(const float4*)&W2s[(j+1)*SH + i];
            c0 += h[i]   * u.x; c1 += h[i+1] * u.y;
            c0 += h[i+2] * u.z; c1 += h[i+3] * u.w;
        }
        iso0 += fmaxf(0.f, a0 + a1) * W3s[j];
        iso1 += fmaxf(0.f, c0 + c1) * W3s[j+1];
    }
    d_ciso[m0 + tid] = iso0 + iso1;
}

// ======================= TF32 MMA GEMMs (unchanged core) =======================
#define STS_A(buf) {                                                      \
    As[buf][skb+0][sm]=f2tf32(ra0.x); As[buf][skb+1][sm]=f2tf32(ra0.y);   \
    As[buf][skb+2][sm]=f2tf32(ra0.z); As[buf][skb+3][sm]=f2tf32(ra0.w);   \
    As[buf][skb+4][sm]=f2tf32(ra1.x); As[buf][skb+5][sm]=f2tf32(ra1.y);   \
    As[buf][skb+6][sm]=f2tf32(ra1.z); As[buf][skb+7][sm]=f2tf32(ra1.w); }

#define STS_B(buf) {                                                      \
    Bs[buf][skb+0][sm]=f2tf32(rb0.x); Bs[buf][skb+1][sm]=f2tf32(rb0.y);   \
    Bs[buf][skb+2][sm]=f2tf32(rb0.z); Bs[buf][skb+3][sm]=f2tf32(rb0.w);   \
    Bs[buf][skb+4][sm]=f2tf32(rb1.x); Bs[buf][skb+5][sm]=f2tf32(rb1.y);   \
    Bs[buf][skb+6][sm]=f2tf32(rb1.z); Bs[buf][skb+7][sm]=f2tf32(rb1.w); }

#define COMPUTE_CHUNK(cur) {                                              \
    _Pragma("unroll")                                                     \
    for (int kk = 0; kk < 16; kk += 8) {                                  \
        uint32_t af[2][4], bf[8][2];                                      \
        _Pragma("unroll")                                                 \
        for (int mf = 0; mf < 2; mf++) {                                  \
            int mb = wm + mf*16 + g;                                      \
            af[mf][0] = As[cur][kk+tq  ][mb];                             \
            af[mf][1] = As[cur][kk+tq  ][mb+8];                           \
            af[mf][2] = As[cur][kk+tq+4][mb];                             \
            af[mf][3] = As[cur][kk+tq+4][mb+8];                           \
        }                                                                 \
        _Pragma("unroll")                                                 \
        for (int nf = 0; nf < 8; nf++) {                                  \
            int nb = wn + nf*8 + g;                                       \
            bf[nf][0] = Bs[cur][kk+tq  ][nb];                             \
            bf[nf][1] = Bs[cur][kk+tq+4][nb];                             \
        }                                                                 \
        _Pragma("unroll")                                                 \
        for (int mf = 0; mf < 2; mf++)                                    \
            _Pragma("unroll")                                             \
            for (int nf = 0; nf < 8; nf++)                                \
                mma_tf32(acc[mf][nf], af[mf], bf[nf]);                    \
    } }

// ---------------- GEMM1 ----------------
__global__ __launch_bounds__(256) void k_gemm1(
    const float* __restrict__ A_W1, const float* __restrict__ A_b1,
    const float* __restrict__ A_W2, const float* __restrict__ A_b2)
{
    int m0 = blockIdx.y * 128;
    if (m0 >= d_off[NSEG]) return;
    int s = 0;
    while (m0 >= d_off[s+1]) s++;
    int e = s & 7;
    int n0 = blockIdx.x * 128;

    __shared__ uint32_t As[2][16][136];
    __shared__ uint32_t Bs[2][16][136];
    __shared__ float s_iso[128];
    __shared__ float s_w1[AH], s_b1v[AH];

    int tid = threadIdx.x;
    int sm = tid & 127, skb = (tid >> 7) * 8;
    int wid = tid >> 5, lane = tid & 31;
    int wm = (wid >> 1) * 32, wn = (wid & 1) * 64;
    int g = lane >> 2, tq = lane & 3;

    if (tid < 128) s_iso[tid] = d_ciso[m0 + tid];
    s_w1[tid]  = A_W1[e*AH + tid];
    s_b1v[tid] = A_b1[e*AH + tid];
    __syncthreads();

    const float* Bbase = A_W2 + ((size_t)e*AH + n0 + sm) * AH + skb;
    float iso = s_iso[sm];

    float4 rb0, rb1;
    rb0 = *(const float4*)(Bbase);
    rb1 = *(const float4*)(Bbase + 4);
    #pragma unroll
    for (int i = 0; i < 8; i++) {
        float v = fmaxf(0.f, iso * s_w1[skb+i] + s_b1v[skb+i]);
        As[0][skb+i][sm] = f2tf32(v);
    }
    STS_B(0);
    __syncthreads();

    float acc[2][8][4];
    #pragma unroll
    for (int mf = 0; mf < 2; mf++)
        #pragma unroll
        for (int nf = 0; nf < 8; nf++)
            #pragma unroll
            for (int i = 0; i < 4; i++) acc[mf][nf][i] = 0.f;

    for (int c = 0; c < 16; c++) {
        int cur = c & 1;
        if (c + 1 < 16) {
            rb0 = *(const float4*)(Bbase + (c+1)*16);
            rb1 = *(const float4*)(Bbase + (c+1)*16 + 4);
        }
        COMPUTE_CHUNK(cur);
        if (c + 1 < 16) {
            int nxt = cur ^ 1;
            int kb2 = (c+1)*16 + skb;
            #pragma unroll
            for (int i = 0; i < 8; i++) {
                float v = fmaxf(0.f, iso * s_w1[kb2+i] + s_b1v[kb2+i]);
                As[nxt][skb+i][sm] = f2tf32(v);
            }
            STS_B(nxt);
        }
        __syncthreads();
    }

    const float* b2p = A_b2 + e*AH + n0 + wn;
    #pragma unroll
    for (int mf = 0; mf < 2; mf++) {
        #pragma unroll
        for (int h = 0; h < 2; h++) {
            int row = m0 + wm + mf*16 + g + h*8;
            float* dst = d_A2 + (size_t)row * AH + n0 + wn;
            #pragma unroll
            for (int nf = 0; nf < 8; nf++) {
                int col = nf*8 + 2*tq;
                float2 v;
                v.x = fmaxf(0.f, acc[mf][nf][2*h+0] + b2p[col]);
                v.y = fmaxf(0.f, acc[mf][nf][2*h+1] + b2p[col+1]);
                *(float2*)&dst[col] = v;
            }
        }
    }
}

// ---------------- GEMM2 ----------------
template<int PASS>
__global__ __launch_bounds__(256) void k_gemm2(
    const float* __restrict__ A_W3, const float* __restrict__ A_b3,
    float* __restrict__ out)
{
    int base = (PASS == 0) ? 0 : d_off[8];
    int lim  = (PASS == 0) ? d_off[8] : d_off[NSEG];
    int m0 = base + blockIdx.y * 128;
    if (m0 >= lim) return;
    int s = 0;
    while (m0 >= d_off[s+1]) s++;
    int e = s & 7;
    int n0 = blockIdx.x * 128;

    __shared__ uint32_t As[2][16][136];
    __shared__ uint32_t Bs[2][16][136];
    __shared__ int   s_tok[128];
    __shared__ float s_gt[128];

    int tid = threadIdx.x;
    int sm = tid & 127, skb = (tid >> 7) * 8;
    int wid = tid >> 5, lane = tid & 31;
    int wm = (wid >> 1) * 32, wn = (wid & 1) * 64;
    int g = lane >> 2, tq = lane & 3;

    if (tid < 128) { s_tok[tid] = d_crow[m0 + tid]; s_gt[tid] = d_cgate[m0 + tid]; }

    const float* Abase = d_A2 + (size_t)(m0 + sm) * AH + skb;
    const float* Bbase = A_W3 + ((size_t)e*GOUT + n0 + sm) * AH + skb;

    float4 ra0, ra1, rb0, rb1;
    ra0 = *(const float4*)(Abase); ra1 = *(const float4*)(Abase + 4);
    rb0 = *(const float4*)(Bbase); rb1 = *(const float4*)(Bbase + 4);
    STS_A(0); STS_B(0);
    __syncthreads();

    float acc[2][8][4];
    #pragma unroll
    for (int mf = 0; mf < 2; mf++)
        #pragma unroll
        for (int nf = 0; nf < 8; nf++)
            #pragma unroll
            for (int i = 0; i < 4; i++) acc[mf][nf][i] = 0.f;

    for (int c = 0; c < 16; c++) {
        int cur = c & 1;
        if (c + 1 < 16) {
            ra0 = *(const float4*)(Abase + (c+1)*16);
            ra1 = *(const float4*)(Abase + (c+1)*16 + 4);
            rb0 = *(const float4*)(Bbase + (c+1)*16);
            rb1 = *(const float4*)(Bbase + (c+1)*16 + 4);
        }
        COMPUTE_CHUNK(cur);
        if (c + 1 < 16) {
            int nxt = cur ^ 1;
            STS_A(nxt); STS_B(nxt);
        }
        __syncthreads();
    }

    const float* b3p = A_b3 + e*GOUT + n0 + wn;
    #pragma unroll
    for (int mf = 0; mf < 2; mf++) {
        #pragma unroll
        for (int h = 0; h < 2; h++) {
            int mr = wm + mf*16 + g + h*8;
            int tok = s_tok[mr];
            if (tok < 0) continue;
            float gt = s_gt[mr];
            float* orow = out + (size_t)tok * GOUT + n0 + wn;
            #pragma unroll
            for (int nf = 0; nf < 8; nf++) {
                int col = nf*8 + 2*tq;
                float vx = gt * (acc[mf][nf][2*h+0] + b3p[col]);
                float vy = gt * (acc[mf][nf][2*h+1] + b3p[col+1]);
                if (PASS == 0) {
                    float2 v; v.x = vx; v.y = vy;
                    *(float2*)&orow[col] = v;
                } else {
                    float2 o = *(const float2*)&orow[col];
                    o.x += vx; o.y += vy;
                    *(float2*)&orow[col] = o;
                }
            }
        }
    }
}

// ---------------- launch ----------------
extern "C" void kernel_launch(void* const* d_in, const int* in_sizes, int n_in,
                              void* d_out, int out_size)
{
    const float* x    = (const float*)d_in[0];
    const float* S_W1 = (const float*)d_in[1];
    const float* S_b1 = (const float*)d_in[2];
    const float* S_W2 = (const float*)d_in[3];
    const float* S_b2 = (const float*)d_in[4];
    const float* S_W3 = (const float*)d_in[5];
    const float* S_b3 = (const float*)d_in[6];
    const float* A_W1 = (const float*)d_in[7];
    const float* A_b1 = (const float*)d_in[8];
    const float* A_W2 = (const float*)d_in[9];
    const float* A_b2 = (const float*)d_in[10];
    const float* A_W3 = (const float*)d_in[11];
    const float* A_b3 = (const float*)d_in[12];
    const float* g_W1 = (const float*)d_in[13];
    const float* g_b1 = (const float*)d_in[14];
    const float* g_W2 = (const float*)d_in[15];
    const float* g_b2 = (const float*)d_in[16];
    const float* g_W3 = (const float*)d_in[17];
    const float* g_b3 = (const float*)d_in[18];
    float* out = (float*)d_out;

    k_init<<<1, 32>>>();
    k_gate<<<NTOK/256, 256>>>(x, g_W1, g_b1, g_W2, g_b2, g_W3, g_b3);
    k_prep<<<NTOK/256, 256>>>(x, out, (long long)out_size - 1);
    k_snet<<<MT1, 128>>>(S_W1, S_b1, S_W2, S_b2, S_W3, S_b3);
    k_gemm1<<<dim3(2, MT1), 256>>>(A_W1, A_b1, A_W2, A_b2);
    k_gemm2<0><<<dim3(8, MT2), 256>>>(A_W3, A_b3, out);
    k_gemm2<1><<<dim3(8, MT2), 256>>>(A_W3, A_b3, out);
}

// round 4
// speedup vs baseline: 4.0859x; 1.8682x over previous
#include <cuda_runtime.h>
#include <math.h>
#include <stdint.h>

#define NTOK 65536
#define GOUT 1024
#define NE   8
#define SH   64
#define AH   256
#define GH   64
#define NSEG 16
#define CAP  (131072 + NSEG*128)          // 133120
#define MT1  (CAP/128)                    // 1040
#define MT2  ((NTOK + NE*128)/128)        // 520 per q-group

#define TS   2560                         // floats per stage tile: 128*20
#define DYN1 ((2+4)*TS*4)                 // gemm1 dynamic smem: 61,440 B
#define DYN2 (8*TS*4)                     // gemm2 dynamic smem: 81,920 B

// ---------------- scratch ----------------
__device__ int   d_cnt[NSEG];
__device__ int   d_off[NSEG+1];
__device__ int   d_cursor[NSEG];
__device__ float d_imp[NE];
__device__ int   d_e1[NTOK], d_e2[NTOK];
__device__ float d_g1[NTOK], d_g2[NTOK];
__device__ int    d_crow[CAP];
__device__ float  d_cgate[CAP];
__device__ float2 d_cx[CAP];
__device__ float  d_ciso[CAP];
__device__ float d_A2[(size_t)CAP * AH];
__device__ float d_W2r[NE*AH*AH];         // tf32-rounded W2
__device__ float d_W3r[(size_t)NE*GOUT*AH]; // tf32-rounded W3

// ---------------- helpers ----------------
__device__ __forceinline__ uint32_t f2tf32(float f) {
    uint32_t u;
    asm volatile("cvt.rna.tf32.f32 %0, %1;" : "=r"(u) : "f"(f));
    return u;
}
__device__ __forceinline__ void mma_tf32(float* c, const uint32_t* a, const uint32_t* b) {
    asm volatile(
        "mma.sync.aligned.m16n8k8.row.col.f32.tf32.tf32.f32 "
        "{%0,%1,%2,%3}, {%4,%5,%6,%7}, {%8,%9}, {%0,%1,%2,%3};\n"
        : "+f"(c[0]), "+f"(c[1]), "+f"(c[2]), "+f"(c[3])
        : "r"(a[0]), "r"(a[1]), "r"(a[2]), "r"(a[3]),
          "r"(b[0]), "r"(b[1]));
}
__device__ __forceinline__ void cpa16(uint32_t dst, const void* src) {
    asm volatile("cp.async.ca.shared.global [%0], [%1], 16;" :: "r"(dst), "l"(src));
}
#define CP_COMMIT  asm volatile("cp.async.commit_group;")
#define CP_WAIT2   asm volatile("cp.async.wait_group 2;")

// ---------------- init ----------------
__global__ void k_init() {
    int t = threadIdx.x;
    if (t < NSEG) { d_cnt[t] = 0; d_cursor[t] = 0; }
    if (t < NE)   d_imp[t] = 0.f;
}

// ---------------- pre-round weights to tf32 ----------------
__global__ void k_round(const float* __restrict__ src, float* __restrict__ dst, int n) {
    int i = blockIdx.x * 256 + threadIdx.x;
    if (i < n) dst[i] = __uint_as_float(f2tf32(src[i]));
}

// ---------------- gate ----------------
__global__ __launch_bounds__(256) void k_gate(
    const float* __restrict__ x,
    const float* __restrict__ g_W1, const float* __restrict__ g_b1,
    const float* __restrict__ g_W2, const float* __restrict__ g_b2,
    const float* __restrict__ g_W3, const float* __restrict__ g_b3)
{
    __shared__ float W1s[GH*2], b1s[GH], W2s[GH*GH], b2s[GH], W3Ts[GH*8], b3s[NE];
    __shared__ int   scnt[NSEG];
    __shared__ float simp[NE];
    int tid = threadIdx.x;

    for (int i = tid; i < GH*2;  i += 256) W1s[i] = g_W1[i];
    for (int i = tid; i < GH;    i += 256) { b1s[i] = g_b1[i]; b2s[i] = g_b2[i]; }
    for (int i = tid; i < GH*GH; i += 256) W2s[i] = g_W2[i];
    for (int i = tid; i < NE*GH; i += 256) W3Ts[(i & 63)*8 + (i >> 6)] = g_W3[i];
    if (tid < NE) { b3s[tid] = g_b3[tid]; simp[tid] = 0.f; }
    if (tid < NSEG) scnt[tid] = 0;
    __syncthreads();

    int t = blockIdx.x * 256 + tid;
    float2 xv = *(const float2*)&x[2*t];
    float x0 = xv.x, x1 = xv.y;

    float h[GH];
    #pragma unroll
    for (int i = 0; i < GH; i++)
        h[i] = fmaxf(0.f, x0 * W1s[2*i] + x1 * W1s[2*i+1] + b1s[i]);

    float lg[NE];
    #pragma unroll
    for (int e = 0; e < NE; e++) lg[e] = b3s[e];

    for (int j = 0; j < GH; j++) {
        float a0 = b2s[j], a1 = 0.f, a2 = 0.f, a3 = 0.f;
        #pragma unroll
        for (int i = 0; i < GH; i += 4) {
            float4 w = *(const float4*)&W2s[j*GH + i];
            a0 += h[i]   * w.x; a1 += h[i+1] * w.y;
            a2 += h[i+2] * w.z; a3 += h[i+3] * w.w;
        }
        float aj = fmaxf(0.f, (a0 + a1) + (a2 + a3));
        float4 wa = *(const float4*)&W3Ts[j*8];
        float4 wb = *(const float4*)&W3Ts[j*8 + 4];
        lg[0] += aj*wa.x; lg[1] += aj*wa.y; lg[2] += aj*wa.z; lg[3] += aj*wa.w;
        lg[4] += aj*wb.x; lg[5] += aj*wb.y; lg[6] += aj*wb.z; lg[7] += aj*wb.w;
    }

    int b1i = 0; float v1 = lg[0];
    #pragma unroll
    for (int e = 1; e < NE; e++) if (lg[e] > v1) { v1 = lg[e]; b1i = e; }
    int b2i = -1; float v2 = -1e30f;
    #pragma unroll
    for (int e = 0; e < NE; e++) if (e != b1i && lg[e] > v2) { v2 = lg[e]; b2i = e; }
    float ed  = __expf(v2 - v1);
    float den = 1.f + ed;
    float g1 = 1.f / den, g2 = ed / den;

    d_e1[t] = b1i; d_e2[t] = b2i; d_g1[t] = g1; d_g2[t] = g2;

    atomicAdd(&scnt[b1i], 1);
    atomicAdd(&scnt[8 + b2i], 1);
    atomicAdd(&simp[b1i], g1);
    atomicAdd(&simp[b2i], g2);
    __syncthreads();
    if (tid < NSEG && scnt[tid]) atomicAdd(&d_cnt[tid], scnt[tid]);
    if (tid < NE) atomicAdd(&d_imp[tid], simp[tid]);
}

// ---------------- prep: offsets + warp-aggregated scatter + padding + loss ----------------
__global__ __launch_bounds__(256) void k_prep(
    const float* __restrict__ x, float* __restrict__ out, long long loss_idx)
{
    __shared__ int soff[NSEG+1], scnt[NSEG];
    int tid = threadIdx.x;
    if (tid == 0) {
        int o = 0;
        for (int s = 0; s < NSEG; s++) {
            scnt[s] = d_cnt[s];
            soff[s] = o;
            o += ((scnt[s] + 127) / 128) * 128;
        }
        soff[NSEG] = o;
    }
    __syncthreads();

    int t = blockIdx.x * 256 + tid;
    int e1 = d_e1[t], e2 = d_e2[t];
    float2 xv = *(const float2*)&x[2*t];
    int lane = tid & 31;
    unsigned lt = (1u << lane) - 1u;

    #pragma unroll
    for (int e = 0; e < NE; e++) {
        unsigned m = __ballot_sync(0xffffffffu, e1 == e);
        if (m) {
            int leader = __ffs(m) - 1;
            int base = 0;
            if (lane == leader) base = atomicAdd(&d_cursor[e], __popc(m));
            base = __shfl_sync(0xffffffffu, base, leader);
            if (e1 == e) {
                int p = soff[e] + base + __popc(m & lt);
                d_crow[p] = t; d_cgate[p] = d_g1[t]; d_cx[p] = xv;
            }
        }
        unsigned m2 = __ballot_sync(0xffffffffu, e2 == e);
        if (m2) {
            int leader = __ffs(m2) - 1;
            int base = 0;
            if (lane == leader) base = atomicAdd(&d_cursor[8 + e], __popc(m2));
            base = __shfl_sync(0xffffffffu, base, leader);
            if (e2 == e) {
                int p = soff[8 + e] + base + __popc(m2 & lt);
                d_crow[p] = t; d_cgate[p] = d_g2[t]; d_cx[p] = xv;
            }
        }
    }

    if (blockIdx.x == 0) {
        if (tid <= NSEG) d_off[tid] = soff[tid];
        for (int s = 0; s < NSEG; s++) {
            int b  = soff[s] + scnt[s];
            int en = soff[s+1];
            for (int i = b + tid; i < en; i += 256) {
                d_crow[i] = -1; d_cgate[i] = 0.f;
                d_cx[i] = make_float2(0.f, 0.f);
            }
        }
        if (tid == 0) {
            float mi = 0.f, ml = 0.f, ld[NE];
            for (int e = 0; e < NE; e++) {
                ld[e] = (float)(scnt[e] + scnt[8 + e]);
                mi += d_imp[e]; ml += ld[e];
            }
            mi /= (float)NE; ml /= (float)NE;
            float vi = 0.f, vl = 0.f;
            for (int e = 0; e < NE; e++) {
                float di = d_imp[e] - mi; vi += di * di;
                float dl = ld[e] - ml;    vl += dl * dl;
            }
            vi /= (float)(NE - 1); vl /= (float)(NE - 1);
            out[loss_idx] = (vi / (mi*mi + 1e-10f) + vl / (ml*ml + 1e-10f)) * 0.01f;
        }
    }
}

// ---------------- S-net on compact rows ----------------
__global__ __launch_bounds__(128) void k_snet(
    const float* __restrict__ S_W1, const float* __restrict__ S_b1,
    const float* __restrict__ S_W2, const float* __restrict__ S_b2,
    const float* __restrict__ S_W3, const float* __restrict__ S_b3)
{
    int m0 = blockIdx.x * 128;
    if (m0 >= d_off[NSEG]) return;
    int s = 0;
    while (m0 >= d_off[s+1]) s++;
    int e = s & 7;

    __shared__ float W1s[SH*2], b1s[SH], W2s[SH*SH], b2s[SH], W3s[SH];
    __shared__ float b3sh;
    int tid = threadIdx.x;
    for (int i = tid; i < SH*2;  i += 128) W1s[i] = S_W1[e*SH*2 + i];
    for (int i = tid; i < SH;    i += 128) {
        b1s[i] = S_b1[e*SH + i]; b2s[i] = S_b2[e*SH + i]; W3s[i] = S_W3[e*SH + i];
    }
    for (int i = tid; i < SH*SH; i += 128) W2s[i] = S_W2[(size_t)e*SH*SH + i];
    if (tid == 0) b3sh = S_b3[e];
    __syncthreads();

    float2 xv = d_cx[m0 + tid];
    float x0 = xv.x, x1 = xv.y;

    float h[SH];
    #pragma unroll
    for (int i = 0; i < SH; i++)
        h[i] = fmaxf(0.f, x0 * W1s[2*i] + x1 * W1s[2*i+1] + b1s[i]);

    float iso0 = b3sh, iso1 = 0.f;
    for (int j = 0; j < SH; j += 2) {
        float a0 = b2s[j], a1 = 0.f, c0 = b2s[j+1], c1 = 0.f;
        #pragma unroll
        for (int i = 0; i < SH; i += 4) {
            float4 w = *(const float4*)&W2s[j*SH + i];
            a0 += h[i]   * w.x; a1 += h[i+1] * w.y;
            a0 += h[i+2] * w.z; a1 += h[i+3] * w.w;
            float4 u = *(const float4*)&W2s[(j+1)*SH + i];
            c0 += h[i]   * u.x; c1 += h[i+1] * u.y;
            c0 += h[i+2] * u.z; c1 += h[i+3] * u.w;
        }
        iso0 += fmaxf(0.f, a0 + a1) * W3s[j];
        iso1 += fmaxf(0.f, c0 + c1) * W3s[j+1];
    }
    d_ciso[m0 + tid] = iso0 + iso1;
}

// ======================= TF32 MMA GEMMs, cp.async 4-stage =======================
// smem tiles [m/n=128][k=16] with row stride 20 (bank-exact 20g+tq pattern).

#define COMPUTE_TILE(Af, Bf) {                                            \
    _Pragma("unroll")                                                     \
    for (int kk = 0; kk < 16; kk += 8) {                                  \
        uint32_t af[2][4], bf[8][2];                                      \
        _Pragma("unroll")                                                 \
        for (int mf = 0; mf < 2; mf++) {                                  \
            int mb = (wm + mf*16 + g) * 20;                               \
            af[mf][0] = __float_as_uint((Af)[mb + kk + tq]);              \
            af[mf][1] = __float_as_uint((Af)[mb + 160 + kk + tq]);        \
            af[mf][2] = __float_as_uint((Af)[mb + kk + tq + 4]);          \
            af[mf][3] = __float_as_uint((Af)[mb + 160 + kk + tq + 4]);    \
        }                                                                 \
        _Pragma("unroll")                                                 \
        for (int nf = 0; nf < 8; nf++) {                                  \
            int nb = (wn + nf*8 + g) * 20;                                \
            bf[nf][0] = __float_as_uint((Bf)[nb + kk + tq]);              \
            bf[nf][1] = __float_as_uint((Bf)[nb + kk + tq + 4]);          \
        }                                                                 \
        _Pragma("unroll")                                                 \
        for (int mf = 0; mf < 2; mf++)                                    \
            _Pragma("unroll")                                             \
            for (int nf = 0; nf < 8; nf++)                                \
                mma_tf32(acc[mf][nf], af[mf], bf[nf]);                    \
    } }

// ---------------- GEMM1: A2 = relu(relu(iso*W1+b1) @ W2r^T + b2) ----------------
__global__ __launch_bounds__(256) void k_gemm1(
    const float* __restrict__ A_W1, const float* __restrict__ A_b1,
    const float* __restrict__ A_b2)
{
    int m0 = blockIdx.y * 128;
    if (m0 >= d_off[NSEG]) return;
    int s = 0;
    while (m0 >= d_off[s+1]) s++;
    int e = s & 7;
    int n0 = blockIdx.x * 128;

    extern __shared__ float smem_f[];
    float* As = smem_f;            // 2 stages
    float* Bs = smem_f + 2*TS;     // 4 stages
    __shared__ float s_iso[128];
    __shared__ float s_w1[AH], s_b1v[AH];

    int tid = threadIdx.x;
    int wid = tid >> 5, lane = tid & 31;
    int wm = (wid >> 1) * 32, wn = (wid & 1) * 64;
    int g = lane >> 2, tq = lane & 3;
    int r0 = tid >> 2, kq = tid & 3;

    if (tid < 128) s_iso[tid] = d_ciso[m0 + tid];
    s_w1[tid]  = A_W1[e*AH + tid];
    s_b1v[tid] = A_b1[e*AH + tid];
    __syncthreads();  // s_iso/s_w1 needed by A-gen below

    uint32_t Bs_u = (uint32_t)__cvta_generic_to_shared(Bs);
    const float* Bg = d_W2r + ((size_t)e*AH + n0) * AH + kq*4;

    // prologue: B stages 0..2, A buffer 0
    #pragma unroll
    for (int st = 0; st < 3; st++) {
        cpa16(Bs_u + (st*TS + r0*20 + kq*4)*4,       Bg + (size_t)r0*AH + st*16);
        cpa16(Bs_u + (st*TS + (r0+64)*20 + kq*4)*4,  Bg + (size_t)(r0+64)*AH + st*16);
        CP_COMMIT;
    }
    {
        float i0 = s_iso[r0], i1 = s_iso[r0+64];
        float4 v0, v1;
        #pragma unroll
        for (int i = 0; i < 4; i++) {
            float w = s_w1[kq*4+i], b = s_b1v[kq*4+i];
            ((float*)&v0)[i] = __uint_as_float(f2tf32(fmaxf(0.f, i0*w + b)));
            ((float*)&v1)[i] = __uint_as_float(f2tf32(fmaxf(0.f, i1*w + b)));
        }
        *(float4*)&As[r0*20 + kq*4] = v0;
        *(float4*)&As[(r0+64)*20 + kq*4] = v1;
    }

    float acc[2][8][4];
    #pragma unroll
    for (int mf = 0; mf < 2; mf++)
        #pragma unroll
        for (int nf = 0; nf < 8; nf++)
            #pragma unroll
            for (int i = 0; i < 4; i++) acc[mf][nf][i] = 0.f;

    for (int c = 0; c < 16; c++) {
        CP_WAIT2;
        __syncthreads();
        COMPUTE_TILE(As + (c & 1)*TS, Bs + (c & 3)*TS);
        if (c + 1 < 16) {
            int kb = (c+1)*16 + kq*4;
            float* Ad = As + ((c+1) & 1)*TS;
            float i0 = s_iso[r0], i1 = s_iso[r0+64];
            float4 v0, v1;
            #pragma unroll
            for (int i = 0; i < 4; i++) {
                float w = s_w1[kb+i], b = s_b1v[kb+i];
                ((float*)&v0)[i] = __uint_as_float(f2tf32(fmaxf(0.f, i0*w + b)));
                ((float*)&v1)[i] = __uint_as_float(f2tf32(fmaxf(0.f, i1*w + b)));
            }
            *(float4*)&Ad[r0*20 + kq*4] = v0;
            *(float4*)&Ad[(r0+64)*20 + kq*4] = v1;
        }
        if (c + 3 < 16) {
            int st = (c+3) & 3, kb = (c+3)*16;
            cpa16(Bs_u + (st*TS + r0*20 + kq*4)*4,      Bg + (size_t)r0*AH + kb);
            cpa16(Bs_u + (st*TS + (r0+64)*20 + kq*4)*4, Bg + (size_t)(r0+64)*AH + kb);
        }
        CP_COMMIT;
    }

    const float* b2p = A_b2 + e*AH + n0 + wn;
    #pragma unroll
    for (int mf = 0; mf < 2; mf++) {
        #pragma unroll
        for (int h = 0; h < 2; h++) {
            int row = m0 + wm + mf*16 + g + h*8;
            float* dst = d_A2 + (size_t)row * AH + n0 + wn;
            #pragma unroll
            for (int nf = 0; nf < 8; nf++) {
                int col = nf*8 + 2*tq;
                float2 v;
                v.x = __uint_as_float(f2tf32(fmaxf(0.f, acc[mf][nf][2*h+0] + b2p[col])));
                v.y = __uint_as_float(f2tf32(fmaxf(0.f, acc[mf][nf][2*h+1] + b2p[col+1])));
                *(float2*)&dst[col] = v;
            }
        }
    }
}

// ---------------- GEMM2: out rows; PASS 0: store, PASS 1: load-add-store -------
template<int PASS>
__global__ __launch_bounds__(256) void k_gemm2(
    const float* __restrict__ A_b3, float* __restrict__ out)
{
    int base = (PASS == 0) ? 0 : d_off[8];
    int lim  = (PASS == 0) ? d_off[8] : d_off[NSEG];
    int m0 = base + blockIdx.y * 128;
    if (m0 >= lim) return;
    int s = 0;
    while (m0 >= d_off[s+1]) s++;
    int e = s & 7;
    int n0 = blockIdx.x * 128;

    extern __shared__ float smem_f[];
    float* As = smem_f;            // 4 stages
    float* Bs = smem_f + 4*TS;     // 4 stages
    __shared__ int   s_tok[128];
    __shared__ float s_gt[128];

    int tid = threadIdx.x;
    int wid = tid >> 5, lane = tid & 31;
    int wm = (wid >> 1) * 32, wn = (wid & 1) * 64;
    int g = lane >> 2, tq = lane & 3;
    int r0 = tid >> 2, kq = tid & 3;

    if (tid < 128) { s_tok[tid] = d_crow[m0 + tid]; s_gt[tid] = d_cgate[m0 + tid]; }

    uint32_t As_u = (uint32_t)__cvta_generic_to_shared(As);
    uint32_t Bs_u = (uint32_t)__cvta_generic_to_shared(Bs);
    const float* Ag = d_A2 + (size_t)m0 * AH + kq*4;
    const float* Bg = d_W3r + ((size_t)e*GOUT + n0) * AH + kq*4;

    #pragma unroll
    for (int st = 0; st < 3; st++) {
        cpa16(As_u + (st*TS + r0*20 + kq*4)*4,      Ag + (size_t)r0*AH + st*16);
        cpa16(As_u + (st*TS + (r0+64)*20 + kq*4)*4, Ag + (size_t)(r0+64)*AH + st*16);
        cpa16(Bs_u + (st*TS + r0*20 + kq*4)*4,      Bg + (size_t)r0*AH + st*16);
        cpa16(Bs_u + (st*TS + (r0+64)*20 + kq*4)*4, Bg + (size_t)(r0+64)*AH + st*16);
        CP_COMMIT;
    }

    float acc[2][8][4];
    #pragma unroll
    for (int mf = 0; mf < 2; mf++)
        #pragma unroll
        for (int nf = 0; nf < 8; nf++)
            #pragma unroll
            for (int i = 0; i < 4; i++) acc[mf][nf][i] = 0.f;

    for (int c = 0; c < 16; c++) {
        CP_WAIT2;
        __syncthreads();
        COMPUTE_TILE(As + (c & 3)*TS, Bs + (c & 3)*TS);
        if (c + 3 < 16) {
            int st = (c+3) & 3, kb = (c+3)*16;
            cpa16(As_u + (st*TS + r0*20 + kq*4)*4,      Ag + (size_t)r0*AH + kb);
            cpa16(As_u + (st*TS + (r0+64)*20 + kq*4)*4, Ag + (size_t)(r0+64)*AH + kb);
            cpa16(Bs_u + (st*TS + r0*20 + kq*4)*4,      Bg + (size_t)r0*AH + kb);
            cpa16(Bs_u + (st*TS + (r0+64)*20 + kq*4)*4, Bg + (size_t)(r0+64)*AH + kb);
        }
        CP_COMMIT;
    }

    const float* b3p = A_b3 + e*GOUT + n0 + wn;
    #pragma unroll
    for (int mf = 0; mf < 2; mf++) {
        #pragma unroll
        for (int h = 0; h < 2; h++) {
            int mr = wm + mf*16 + g + h*8;
            int tok = s_tok[mr];
            if (tok < 0) continue;
            float gt = s_gt[mr];
            float* orow = out + (size_t)tok * GOUT + n0 + wn;
            #pragma unroll
            for (int nf = 0; nf < 8; nf++) {
                int col = nf*8 + 2*tq;
                float vx = gt * (acc[mf][nf][2*h+0] + b3p[col]);
                float vy = gt * (acc[mf][nf][2*h+1] + b3p[col+1]);
                if (PASS == 0) {
                    float2 v; v.x = vx; v.y = vy;
                    *(float2*)&orow[col] = v;
                } else {
                    float2 o = *(const float2*)&orow[col];
                    o.x += vx; o.y += vy;
                    *(float2*)&orow[col] = o;
                }
            }
        }
    }
}

// ---------------- launch ----------------
extern "C" void kernel_launch(void* const* d_in, const int* in_sizes, int n_in,
                              void* d_out, int out_size)
{
    const float* x    = (const float*)d_in[0];
    const float* S_W1 = (const float*)d_in[1];
    const float* S_b1 = (const float*)d_in[2];
    const float* S_W2 = (const float*)d_in[3];
    const float* S_b2 = (const float*)d_in[4];
    const float* S_W3 = (const float*)d_in[5];
    const float* S_b3 = (const float*)d_in[6];
    const float* A_W1 = (const float*)d_in[7];
    const float* A_b1 = (const float*)d_in[8];
    const float* A_W2 = (const float*)d_in[9];
    const float* A_b2 = (const float*)d_in[10];
    const float* A_W3 = (const float*)d_in[11];
    const float* A_b3 = (const float*)d_in[12];
    const float* g_W1 = (const float*)d_in[13];
    const float* g_b1 = (const float*)d_in[14];
    const float* g_W2 = (const float*)d_in[15];
    const float* g_b2 = (const float*)d_in[16];
    const float* g_W3 = (const float*)d_in[17];
    const float* g_b3 = (const float*)d_in[18];
    float* out = (float*)d_out;

    cudaFuncSetAttribute(k_gemm1,    cudaFuncAttributeMaxDynamicSharedMemorySize, DYN1);
    cudaFuncSetAttribute(k_gemm2<0>, cudaFuncAttributeMaxDynamicSharedMemorySize, DYN2);
    cudaFuncSetAttribute(k_gemm2<1>, cudaFuncAttributeMaxDynamicSharedMemorySize, DYN2);

    float* w2r; cudaGetSymbolAddress((void**)&w2r, d_W2r);
    float* w3r; cudaGetSymbolAddress((void**)&w3r, d_W3r);

    k_init<<<1, 32>>>();
    k_round<<<(NE*AH*AH + 255)/256, 256>>>(A_W2, w2r, NE*AH*AH);
    k_round<<<(NE*GOUT*AH + 255)/256, 256>>>(A_W3, w3r, NE*GOUT*AH);
    k_gate<<<NTOK/256, 256>>>(x, g_W1, g_b1, g_W2, g_b2, g_W3, g_b3);
    k_prep<<<NTOK/256, 256>>>(x, out, (long long)out_size - 1);
    k_snet<<<MT1, 128>>>(S_W1, S_b1, S_W2, S_b2, S_W3, S_b3);
    k_gemm1<<<dim3(2, MT1), 256, DYN1>>>(A_W1, A_b1, A_b2);
    k_gemm2<0><<<dim3(8, MT2), 256, DYN2>>>(A_b3, out);
    k_gemm2<1><<<dim3(8, MT2), 256, DYN2>>>(A_b3, out);
}